// round 15
// baseline (speedup 1.0000x reference)
#include <cuda_runtime.h>
#include <math.h>
#include <stdint.h>

#define Nn 30000
#define Ee 300000
#define Hd 128
#define H3 384
#define Rr 200
#define SLOPE 0.22916666666666666f

// ---------------- scratch (__device__ globals; allocation-free) ----------------
__device__ __align__(16) unsigned char g_mask[(size_t)Rr * Nn];   // 6 MB
__device__ float g_deg[Nn];
__device__ float g_relsum[Rr * Hd];
__device__ int   g_relcnt[Rr];
__device__ int   g_roff[Rr + 1];
__device__ int   g_rfill[Rr];
__device__ int   g_rlist[2 * Ee];
__device__ __align__(16) float g_rel[Rr * Hd];
__device__ __align__(16) float g_agg[(size_t)Nn * Hd];
__device__ __align__(16) float g_nf[(size_t)Nn * Hd];
__device__ __align__(16) float g_ef[(size_t)Ee * Hd];
// factorization tables
__device__ __align__(16) float g_M[H3 * H3];          // Wih @ W2  [384,384]
__device__ __align__(16) float g_bc[H3];              // Wih @ b2 + bih
__device__ __align__(16) float g_Gs[(size_t)Nn * H3];
__device__ __align__(16) float g_Gd[(size_t)Nn * H3];
__device__ __align__(16) float g_Qs[(size_t)Nn * Hd];
__device__ __align__(16) float g_Grel[Rr * H3];
__device__ __align__(16) float g_Qrel[Rr * Hd];
__device__ __align__(16) float g_gh[(size_t)Ee * 512]; // [0:384)=ef@Whh^T, [384:512)=ef@W1c^T
__device__ __align__(16) float g_emsg[(size_t)Ee * Hd];
__device__ __align__(16) float g_Wcomb[512 * Hd];      // rows 0:384 = Whh, 384:512 = W1c

// ---------------- zero kernels ----------------
__global__ void zero_mask_deg_k() {
    size_t tid = (size_t)blockIdx.x * blockDim.x + threadIdx.x;
    size_t st = (size_t)gridDim.x * blockDim.x;
    uint32_t* m = (uint32_t*)g_mask;
    size_t mw = (size_t)Rr * Nn / 4;
    for (size_t i = tid; i < mw; i += st) m[i] = 0u;
    for (size_t i = tid; i < Nn; i += st) g_deg[i] = 0.f;
}

__global__ void zero_agg_rel_k() {
    size_t tid = (size_t)blockIdx.x * blockDim.x + threadIdx.x;
    size_t st = (size_t)gridDim.x * blockDim.x;
    size_t na = (size_t)Nn * Hd;
    for (size_t i = tid; i < na; i += st) g_agg[i] = 0.f;
    for (size_t i = tid; i < (size_t)Rr * Hd; i += st) g_relsum[i] = 0.f;
}

// ---------------- graph structure (built once; layer-invariant) ----------------
__global__ void build_mask_k(const int* __restrict__ src, const int* __restrict__ dst,
                             const int* __restrict__ ety) {
    int e = blockIdx.x * blockDim.x + threadIdx.x;
    if (e < Ee) {
        int t = ety[e];
        g_mask[(size_t)t * Nn + src[e]] = 1;
        g_mask[(size_t)t * Nn + dst[e]] = 1;
        atomicAdd(&g_deg[dst[e]], 1.f);
    }
}

__global__ void rel_count_k() {
    int r = blockIdx.x;
    int tid = threadIdx.x;
    const unsigned char* mrow = g_mask + (size_t)r * Nn;
    int cnt = 0;
    for (int n = tid; n < Nn; n += 256) cnt += mrow[n] ? 1 : 0;
    __shared__ int sred[256];
    sred[tid] = cnt;
    __syncthreads();
    for (int s = 128; s > 0; s >>= 1) {
        if (tid < s) sred[tid] += sred[tid + s];
        __syncthreads();
    }
    if (tid == 0) g_relcnt[r] = sred[0];
}

__global__ void rel_scan_k() {
    if (threadIdx.x == 0) {
        int a = 0;
        for (int r = 0; r < Rr; r++) {
            g_roff[r] = a;
            a += g_relcnt[r];
            g_rfill[r] = 0;
        }
        g_roff[Rr] = a;
    }
}

__global__ void rel_fill_k() {
    int r = blockIdx.x;
    const unsigned char* mrow = g_mask + (size_t)r * Nn;
    int base = g_roff[r];
    for (int n = threadIdx.x; n < Nn; n += 256) {
        if (mrow[n]) {
            int p = atomicAdd(&g_rfill[r], 1);
            g_rlist[base + p] = n;
        }
    }
}

__global__ void rel_sum_k(const float* __restrict__ nf) {
    int r = blockIdx.x, part = blockIdx.y, c = threadIdx.x;  // 128 threads
    int beg = g_roff[r], end = g_roff[r + 1];
    int len = end - beg;
    int s0 = beg + (int)(((long long)len * part) >> 3);
    int s1 = beg + (int)(((long long)len * (part + 1)) >> 3);
    __shared__ int sidx[256];
    float acc = 0.f;
    for (int b = s0; b < s1; b += 256) {
        int nb = min(256, s1 - b);
        for (int i = c; i < nb; i += 128) sidx[i] = g_rlist[b + i];
        __syncthreads();
#pragma unroll 4
        for (int i = 0; i < nb; i++) acc += nf[(size_t)sidx[i] * Hd + c];
        __syncthreads();
    }
    if (acc != 0.f) atomicAdd(&g_relsum[r * Hd + c], acc);
}

__global__ void rel_fin_k() {
    int r = blockIdx.x, c = threadIdx.x;
    int cnt = g_roff[r + 1] - g_roff[r];
    g_rel[r * Hd + c] = (cnt > 0) ? g_relsum[r * Hd + c] / (float)cnt : 0.f;
}

// ---------------- weight composition ----------------
__global__ void comp_M_k(const float* __restrict__ Wih, const float* __restrict__ W2) {
    int i = blockIdx.x;
    int j = threadIdx.x;
    __shared__ float wr[Hd];
    if (j < Hd) wr[j] = Wih[(size_t)i * Hd + j];
    __syncthreads();
    float acc = 0.f;
#pragma unroll 8
    for (int h = 0; h < Hd; h++) acc += wr[h] * W2[(size_t)h * H3 + j];
    g_M[i * H3 + j] = acc;
}

__global__ void comp_bc_k(const float* __restrict__ Wih, const float* __restrict__ b2,
                          const float* __restrict__ bih) {
    int i = blockIdx.x * blockDim.x + threadIdx.x;
    if (i < H3) {
        float acc = bih[i];
#pragma unroll 8
        for (int h = 0; h < Hd; h++) acc += Wih[(size_t)i * Hd + h] * b2[h];
        g_bc[i] = acc;
    }
}

// combined weight table: rows 0:384 = Whh (ldw Hd), rows 384:512 = W1 cols 256:384
__global__ void comb_W_k(const float* __restrict__ Whh, const float* __restrict__ W1) {
    int idx = blockIdx.x * 256 + threadIdx.x;
    if (idx < 512 * Hd) {
        int j = idx >> 7, k = idx & 127;
        g_Wcomb[idx] = (j < H3) ? Whh[(size_t)j * Hd + k]
                                : W1[(size_t)(j - H3) * H3 + 256 + k];
    }
}

// ---------------- 3xTF32 tensor-core GEMM ----------------
// grid: (n_tiles, row_tiles) — N fastest for L2 reuse of A row tiles.
#define TCPAD 36
#define TC_SMEM (4 * 128 * TCPAD * 4)   // 73728 bytes

__device__ __forceinline__ uint32_t f2tf32(float x) {
    uint32_t r;
    asm("cvt.rna.tf32.f32 %0, %1;" : "=r"(r) : "f"(x));
    return r;
}

#define MMA_TF32(C, A0, A1, A2, A3, B0, B1)                                        \
    asm volatile(                                                                  \
        "mma.sync.aligned.m16n8k8.row.col.f32.tf32.tf32.f32 "                      \
        "{%0,%1,%2,%3}, {%4,%5,%6,%7}, {%8,%9}, {%0,%1,%2,%3};"                    \
        : "+f"(C[0]), "+f"(C[1]), "+f"(C[2]), "+f"(C[3])                           \
        : "r"(A0), "r"(A1), "r"(A2), "r"(A3), "r"(B0), "r"(B1))

__global__ __launch_bounds__(256, 2) void tc_gemm_k(
    const float* __restrict__ A, int nrows,
    const float* __restrict__ W, int ldw,
    float* __restrict__ out, int ldo) {
    extern __shared__ __align__(16) float ts[];
    float* Ah = ts;                    // [128][TCPAD]
    float* Al = Ah + 128 * TCPAD;
    float* Bh = Al + 128 * TCPAD;
    float* Bl = Bh + 128 * TCPAD;

    int jb = blockIdx.x * 128;
    int r0 = blockIdx.y * 128;
    int tid = threadIdx.x;
    int lane = tid & 31;
    int wid = tid >> 5;
    int wm = (wid & 1) * 64;
    int wn = (wid >> 1) * 32;
    int gg = lane >> 2, qq = lane & 3;

    float c[4][4][4];
#pragma unroll
    for (int mf = 0; mf < 4; mf++)
#pragma unroll
        for (int nf = 0; nf < 4; nf++)
#pragma unroll
            for (int u = 0; u < 4; u++) c[mf][nf][u] = 0.f;

    int lr = tid >> 3;            // 0..31
    int lc = (tid & 7) * 4;       // 0..28

#pragma unroll 1
    for (int s = 0; s < 4; s++) {
        int ks = s * 32;
        __syncthreads();
#pragma unroll
        for (int p = 0; p < 4; p++) {
            int row = p * 32 + lr;
            const float* ap = A + (size_t)min(r0 + row, nrows - 1) * Hd + ks + lc;
            float4 v = *reinterpret_cast<const float4*>(ap);
            const float* wp = W + (size_t)(jb + row) * ldw + ks + lc;
            float4 u = *reinterpret_cast<const float4*>(wp);
            float* ah = &Ah[row * TCPAD + lc];
            float* al = &Al[row * TCPAD + lc];
            float* bh = &Bh[row * TCPAD + lc];
            float* bl = &Bl[row * TCPAD + lc];
            float hx;
            hx = __uint_as_float(f2tf32(v.x)); ah[0] = hx; al[0] = __uint_as_float(f2tf32(v.x - hx));
            hx = __uint_as_float(f2tf32(v.y)); ah[1] = hx; al[1] = __uint_as_float(f2tf32(v.y - hx));
            hx = __uint_as_float(f2tf32(v.z)); ah[2] = hx; al[2] = __uint_as_float(f2tf32(v.z - hx));
            hx = __uint_as_float(f2tf32(v.w)); ah[3] = hx; al[3] = __uint_as_float(f2tf32(v.w - hx));
            hx = __uint_as_float(f2tf32(u.x)); bh[0] = hx; bl[0] = __uint_as_float(f2tf32(u.x - hx));
            hx = __uint_as_float(f2tf32(u.y)); bh[1] = hx; bl[1] = __uint_as_float(f2tf32(u.y - hx));
            hx = __uint_as_float(f2tf32(u.z)); bh[2] = hx; bl[2] = __uint_as_float(f2tf32(u.z - hx));
            hx = __uint_as_float(f2tf32(u.w)); bh[3] = hx; bl[3] = __uint_as_float(f2tf32(u.w - hx));
        }
        __syncthreads();
#pragma unroll
        for (int k8 = 0; k8 < 32; k8 += 8) {
            uint32_t ahf[4][4], alf[4][4];
#pragma unroll
            for (int mf = 0; mf < 4; mf++) {
                int rr = wm + mf * 16 + gg;
                ahf[mf][0] = __float_as_uint(Ah[rr * TCPAD + k8 + qq]);
                ahf[mf][1] = __float_as_uint(Ah[(rr + 8) * TCPAD + k8 + qq]);
                ahf[mf][2] = __float_as_uint(Ah[rr * TCPAD + k8 + qq + 4]);
                ahf[mf][3] = __float_as_uint(Ah[(rr + 8) * TCPAD + k8 + qq + 4]);
                alf[mf][0] = __float_as_uint(Al[rr * TCPAD + k8 + qq]);
                alf[mf][1] = __float_as_uint(Al[(rr + 8) * TCPAD + k8 + qq]);
                alf[mf][2] = __float_as_uint(Al[rr * TCPAD + k8 + qq + 4]);
                alf[mf][3] = __float_as_uint(Al[(rr + 8) * TCPAD + k8 + qq + 4]);
            }
#pragma unroll
            for (int nf = 0; nf < 4; nf++) {
                int nn = wn + nf * 8 + gg;
                uint32_t bh0 = __float_as_uint(Bh[nn * TCPAD + k8 + qq]);
                uint32_t bh1 = __float_as_uint(Bh[nn * TCPAD + k8 + qq + 4]);
                uint32_t bl0 = __float_as_uint(Bl[nn * TCPAD + k8 + qq]);
                uint32_t bl1 = __float_as_uint(Bl[nn * TCPAD + k8 + qq + 4]);
#pragma unroll
                for (int mf = 0; mf < 4; mf++) {
                    MMA_TF32(c[mf][nf], ahf[mf][0], ahf[mf][1], ahf[mf][2], ahf[mf][3], bh0, bh1);
                    MMA_TF32(c[mf][nf], ahf[mf][0], ahf[mf][1], ahf[mf][2], ahf[mf][3], bl0, bl1);
                    MMA_TF32(c[mf][nf], alf[mf][0], alf[mf][1], alf[mf][2], alf[mf][3], bh0, bh1);
                }
            }
        }
    }

#pragma unroll
    for (int mf = 0; mf < 4; mf++) {
        int r = r0 + wm + mf * 16 + gg;
#pragma unroll
        for (int nf = 0; nf < 4; nf++) {
            int cc = jb + wn + nf * 8 + 2 * qq;
            if (r < nrows)
                *reinterpret_cast<float2*>(&out[(size_t)r * ldo + cc]) =
                    make_float2(c[mf][nf][0], c[mf][nf][1]);
            if (r + 8 < nrows)
                *reinterpret_cast<float2*>(&out[(size_t)(r + 8) * ldo + cc]) =
                    make_float2(c[mf][nf][2], c[mf][nf][3]);
        }
    }
}

// ---------------- fused gi2 GEMM + GRU#2: out_ef = GRU(e_msg@Wih^T, gh, ef) ----------------
// 64-edge tile; loops 3 gate tiles internally keeping r/z in registers.
#define GA_PAD 132
#define GRU_TC_SMEM ((2 * 64 * GA_PAD + 2 * 128 * TCPAD) * 4)  // 104448 bytes

__device__ __forceinline__ float sigmoidf_(float x) { return 1.f / (1.f + expf(-x)); }

__global__ __launch_bounds__(256, 1) void tc_gru2_k(
    const float* __restrict__ ef,
    const float* __restrict__ Wih,
    const float* __restrict__ bih, const float* __restrict__ bhh,
    float* __restrict__ out) {
    extern __shared__ __align__(16) float ts[];
    float* Ah = ts;                    // [64][GA_PAD] full K
    float* Al = Ah + 64 * GA_PAD;
    float* Bh = Al + 64 * GA_PAD;      // [128][TCPAD] per k-slice
    float* Bl = Bh + 128 * TCPAD;

    int e0 = blockIdx.x * 64;
    int tid = threadIdx.x;
    int lane = tid & 31;
    int wid = tid >> 5;
    int wm = (wid & 1) * 32;
    int wn = (wid >> 1) * 32;
    int gg = lane >> 2, qq = lane & 3;

    // load + split-convert A (e_msg) 64x128 into full-K smem
#pragma unroll
    for (int p = 0; p < 8; p++) {
        int idx = p * 256 + tid;
        int row = idx >> 5;
        int c4 = (idx & 31) * 4;
        const float* ap = g_emsg + (size_t)min(e0 + row, Ee - 1) * Hd + c4;
        float4 v = *reinterpret_cast<const float4*>(ap);
        float* ah = &Ah[row * GA_PAD + c4];
        float* al = &Al[row * GA_PAD + c4];
        float hx;
        hx = __uint_as_float(f2tf32(v.x)); ah[0] = hx; al[0] = __uint_as_float(f2tf32(v.x - hx));
        hx = __uint_as_float(f2tf32(v.y)); ah[1] = hx; al[1] = __uint_as_float(f2tf32(v.y - hx));
        hx = __uint_as_float(f2tf32(v.z)); ah[2] = hx; al[2] = __uint_as_float(f2tf32(v.z - hx));
        hx = __uint_as_float(f2tf32(v.w)); ah[3] = hx; al[3] = __uint_as_float(f2tf32(v.w - hx));
    }

    float rg_[2][4][4], zg_[2][4][4];
    int lr = tid >> 3;
    int lc = (tid & 7) * 4;

#pragma unroll 1
    for (int g = 0; g < 3; g++) {
        float c[2][4][4];
#pragma unroll
        for (int mf = 0; mf < 2; mf++)
#pragma unroll
            for (int nf = 0; nf < 4; nf++)
#pragma unroll
                for (int u = 0; u < 4; u++) c[mf][nf][u] = 0.f;

#pragma unroll 1
        for (int s = 0; s < 4; s++) {
            int ks = s * 32;
            __syncthreads();   // also covers the A-store -> first-use ordering
#pragma unroll
            for (int p = 0; p < 4; p++) {
                int row = p * 32 + lr;
                const float* wp = Wih + (size_t)(g * Hd + row) * Hd + ks + lc;
                float4 u = *reinterpret_cast<const float4*>(wp);
                float* bh = &Bh[row * TCPAD + lc];
                float* bl = &Bl[row * TCPAD + lc];
                float hx;
                hx = __uint_as_float(f2tf32(u.x)); bh[0] = hx; bl[0] = __uint_as_float(f2tf32(u.x - hx));
                hx = __uint_as_float(f2tf32(u.y)); bh[1] = hx; bl[1] = __uint_as_float(f2tf32(u.y - hx));
                hx = __uint_as_float(f2tf32(u.z)); bh[2] = hx; bl[2] = __uint_as_float(f2tf32(u.z - hx));
                hx = __uint_as_float(f2tf32(u.w)); bh[3] = hx; bl[3] = __uint_as_float(f2tf32(u.w - hx));
            }
            __syncthreads();
#pragma unroll
            for (int k8 = 0; k8 < 32; k8 += 8) {
                uint32_t ahf[2][4], alf[2][4];
#pragma unroll
                for (int mf = 0; mf < 2; mf++) {
                    int rr = wm + mf * 16 + gg;
                    ahf[mf][0] = __float_as_uint(Ah[rr * GA_PAD + ks + k8 + qq]);
                    ahf[mf][1] = __float_as_uint(Ah[(rr + 8) * GA_PAD + ks + k8 + qq]);
                    ahf[mf][2] = __float_as_uint(Ah[rr * GA_PAD + ks + k8 + qq + 4]);
                    ahf[mf][3] = __float_as_uint(Ah[(rr + 8) * GA_PAD + ks + k8 + qq + 4]);
                    alf[mf][0] = __float_as_uint(Al[rr * GA_PAD + ks + k8 + qq]);
                    alf[mf][1] = __float_as_uint(Al[(rr + 8) * GA_PAD + ks + k8 + qq]);
                    alf[mf][2] = __float_as_uint(Al[rr * GA_PAD + ks + k8 + qq + 4]);
                    alf[mf][3] = __float_as_uint(Al[(rr + 8) * GA_PAD + ks + k8 + qq + 4]);
                }
#pragma unroll
                for (int nf = 0; nf < 4; nf++) {
                    int nn = wn + nf * 8 + gg;
                    uint32_t bh0 = __float_as_uint(Bh[nn * TCPAD + k8 + qq]);
                    uint32_t bh1 = __float_as_uint(Bh[nn * TCPAD + k8 + qq + 4]);
                    uint32_t bl0 = __float_as_uint(Bl[nn * TCPAD + k8 + qq]);
                    uint32_t bl1 = __float_as_uint(Bl[nn * TCPAD + k8 + qq + 4]);
#pragma unroll
                    for (int mf = 0; mf < 2; mf++) {
                        MMA_TF32(c[mf][nf], ahf[mf][0], ahf[mf][1], ahf[mf][2], ahf[mf][3], bh0, bh1);
                        MMA_TF32(c[mf][nf], ahf[mf][0], ahf[mf][1], ahf[mf][2], ahf[mf][3], bl0, bl1);
                        MMA_TF32(c[mf][nf], alf[mf][0], alf[mf][1], alf[mf][2], alf[mf][3], bh0, bh1);
                    }
                }
            }
        }

        // gate epilogue
#pragma unroll
        for (int mf = 0; mf < 2; mf++) {
            int rA = wm + mf * 16 + gg;
#pragma unroll
            for (int nf = 0; nf < 4; nf++) {
                int col = wn + nf * 8 + 2 * qq;
#pragma unroll
                for (int u = 0; u < 4; u++) {
                    int rr = rA + (u >> 1) * 8;
                    int cc = col + (u & 1);
                    int e = e0 + rr;
                    size_t ec = (size_t)min(e, Ee - 1);
                    int jg = g * Hd + cc;
                    float gi = c[mf][nf][u] + __ldg(&bih[jg]);
                    float gh = g_gh[ec * 512 + jg] + __ldg(&bhh[jg]);
                    if (g == 0) {
                        rg_[mf][nf][u] = sigmoidf_(gi + gh);
                    } else if (g == 1) {
                        zg_[mf][nf][u] = sigmoidf_(gi + gh);
                    } else {
                        float nn2 = tanhf(gi + rg_[mf][nf][u] * gh);
                        float z = zg_[mf][nf][u];
                        float o = (1.f - z) * nn2 + z * ef[ec * Hd + cc];
                        if (e < Ee) out[(size_t)e * Hd + cc] = o;
                    }
                }
            }
        }
    }
}

// ---------------- node update: rrelu(agg/deg + nf@W3^T + b3) ----------------
__global__ __launch_bounds__(256) void node_update_k(
    const float* __restrict__ nf, const float* __restrict__ W3, const float* __restrict__ b3,
    float* __restrict__ out) {
    __shared__ __align__(16) float As[64][33];
    __shared__ __align__(16) float Bs[32][132];
    int n0 = blockIdx.x * 64;
    int tid = threadIdx.x;
    int tx = tid & 15, ty = tid >> 4;

    float c[4][8];
#pragma unroll
    for (int i = 0; i < 4; i++)
#pragma unroll
        for (int u = 0; u < 8; u++) c[i][u] = 0.f;

    int lcol = tid & 31;
    int lrow = tid >> 5;
    int bj = tid >> 1;
    int bhalf = (tid & 1) * 16;

    for (int k0 = 0; k0 < Hd; k0 += 32) {
#pragma unroll
        for (int i = 0; i < 8; i++) {
            int rr = lrow + i * 8;
            As[rr][lcol] = nf[(size_t)min(n0 + rr, Nn - 1) * Hd + k0 + lcol];
        }
#pragma unroll
        for (int i = 0; i < 4; i++) {
            float4 w = *reinterpret_cast<const float4*>(&W3[(size_t)bj * Hd + k0 + bhalf + i * 4]);
            Bs[bhalf + i * 4 + 0][bj] = w.x;
            Bs[bhalf + i * 4 + 1][bj] = w.y;
            Bs[bhalf + i * 4 + 2][bj] = w.z;
            Bs[bhalf + i * 4 + 3][bj] = w.w;
        }
        __syncthreads();
#pragma unroll
        for (int kk = 0; kk < 32; kk++) {
            float a[4];
#pragma unroll
            for (int i = 0; i < 4; i++) a[i] = As[ty * 4 + i][kk];
            const float4* bp = reinterpret_cast<const float4*>(&Bs[kk][0]);
            float4 b0 = bp[tx], b1 = bp[16 + tx];
#pragma unroll
            for (int i = 0; i < 4; i++) {
                c[i][0] += a[i] * b0.x; c[i][1] += a[i] * b0.y;
                c[i][2] += a[i] * b0.z; c[i][3] += a[i] * b0.w;
                c[i][4] += a[i] * b1.x; c[i][5] += a[i] * b1.y;
                c[i][6] += a[i] * b1.z; c[i][7] += a[i] * b1.w;
            }
        }
        __syncthreads();
    }

#pragma unroll
    for (int i = 0; i < 4; i++) {
        int n = n0 + ty * 4 + i;
        if (n < Nn) {
            float dg = g_deg[n];
            if (dg < 1.f) dg = 1.f;
            float inv = 1.f / dg;
#pragma unroll
            for (int u = 0; u < 8; u++) {
                int j = (u < 4) ? tx * 4 + u : 64 + tx * 4 + (u - 4);
                float v = c[i][u] + __ldg(&b3[j]) + g_agg[(size_t)n * Hd + j] * inv;
                out[(size_t)n * Hd + j] = (v >= 0.f) ? v : SLOPE * v;
            }
        }
    }
}

// ---------------- edge phase A: elementwise GRU#1 + msg atomics -> g_emsg ----------------
__global__ __launch_bounds__(256) void edge_phaseA_k(
    const float* __restrict__ ef,
    const int* __restrict__ src, const int* __restrict__ dst, const int* __restrict__ ety,
    const float* __restrict__ bhh, const float* __restrict__ b1) {
    int gidx = blockIdx.x * 256 + threadIdx.x;
    int e = gidx >> 5, q = gidx & 31;
    if (e >= Ee) return;
    int t = ety[e], s = src[e], d = dst[e];
    size_t ec = (size_t)e;

    const float4* gr = (const float4*)(g_Grel + (size_t)t * H3);
    const float4* gs = (const float4*)(g_Gs + (size_t)s * H3);
    const float4* gd = (const float4*)(g_Gd + (size_t)d * H3);
    const float4* gh = (const float4*)(g_gh + ec * 512);
    const float4* bc4 = (const float4*)g_bc;
    const float4* bh4 = (const float4*)bhh;
    float4 hv = ((const float4*)(ef + ec * Hd))[q];

    float o[4];
    {
        float4 gi0, gi1, gi2v, gh0, gh1, gh2;
        float4 a0 = gr[q],      b0 = gs[q],       c0 = gd[q];
        float4 a1 = gr[32 + q], b1v = gs[32 + q], c1 = gd[32 + q];
        float4 a2 = gr[64 + q], b2v = gs[64 + q], c2 = gd[64 + q];
        float4 e0v = bc4[q], e1v = bc4[32 + q], e2v = bc4[64 + q];
        gi0.x = a0.x + b0.x + c0.x + e0v.x; gi0.y = a0.y + b0.y + c0.y + e0v.y;
        gi0.z = a0.z + b0.z + c0.z + e0v.z; gi0.w = a0.w + b0.w + c0.w + e0v.w;
        gi1.x = a1.x + b1v.x + c1.x + e1v.x; gi1.y = a1.y + b1v.y + c1.y + e1v.y;
        gi1.z = a1.z + b1v.z + c1.z + e1v.z; gi1.w = a1.w + b1v.w + c1.w + e1v.w;
        gi2v.x = a2.x + b2v.x + c2.x + e2v.x; gi2v.y = a2.y + b2v.y + c2.y + e2v.y;
        gi2v.z = a2.z + b2v.z + c2.z + e2v.z; gi2v.w = a2.w + b2v.w + c2.w + e2v.w;
        float4 h0 = gh[q], h1 = gh[32 + q], h2 = gh[64 + q];
        float4 p0 = bh4[q], p1 = bh4[32 + q], p2 = bh4[64 + q];
        gh0.x = h0.x + p0.x; gh0.y = h0.y + p0.y; gh0.z = h0.z + p0.z; gh0.w = h0.w + p0.w;
        gh1.x = h1.x + p1.x; gh1.y = h1.y + p1.y; gh1.z = h1.z + p1.z; gh1.w = h1.w + p1.w;
        gh2.x = h2.x + p2.x; gh2.y = h2.y + p2.y; gh2.z = h2.z + p2.z; gh2.w = h2.w + p2.w;

        float rg, zg, ng;
        rg = sigmoidf_(gi0.x + gh0.x); zg = sigmoidf_(gi1.x + gh1.x);
        ng = tanhf(gi2v.x + rg * gh2.x); o[0] = (1.f - zg) * ng + zg * hv.x;
        rg = sigmoidf_(gi0.y + gh0.y); zg = sigmoidf_(gi1.y + gh1.y);
        ng = tanhf(gi2v.y + rg * gh2.y); o[1] = (1.f - zg) * ng + zg * hv.y;
        rg = sigmoidf_(gi0.z + gh0.z); zg = sigmoidf_(gi1.z + gh1.z);
        ng = tanhf(gi2v.z + rg * gh2.z); o[2] = (1.f - zg) * ng + zg * hv.z;
        rg = sigmoidf_(gi0.w + gh0.w); zg = sigmoidf_(gi1.w + gh1.w);
        ng = tanhf(gi2v.w + rg * gh2.w); o[3] = (1.f - zg) * ng + zg * hv.w;
    }
    *reinterpret_cast<float4*>(g_emsg + ec * Hd + q * 4) = make_float4(o[0], o[1], o[2], o[3]);

    // msg + atomic aggregation (mean divide happens in node_update)
    {
        const float4* qr = (const float4*)(g_Qrel + (size_t)t * Hd);
        const float4* qs = (const float4*)(g_Qs + (size_t)s * Hd);
        float4 me = ((const float4*)(g_gh + ec * 512 + 384))[q];
        float4 bb = ((const float4*)b1)[q];
        float4 qa = qr[q], qb = qs[q];
        float* ap = &g_agg[(size_t)d * Hd + q * 4];
        atomicAdd(ap + 0, qa.x + qb.x + me.x + bb.x);
        atomicAdd(ap + 1, qa.y + qb.y + me.y + bb.y);
        atomicAdd(ap + 2, qa.z + qb.z + me.z + bb.z);
        atomicAdd(ap + 3, qa.w + qb.w + me.w + bb.w);
    }
}

// ---------------- host orchestration ----------------
extern "C" void kernel_launch(void* const* d_in, const int* in_sizes, int n_in,
                              void* d_out, int out_size) {
    const float* nf0 = (const float*)d_in[0];
    const float* ef0 = (const float*)d_in[1];
    const int* src = (const int*)d_in[2];
    const int* dst = (const int*)d_in[3];
    const int* ety = (const int*)d_in[4];
    const float* W1 = (const float*)d_in[5];
    const float* b1 = (const float*)d_in[6];
    const float* W2 = (const float*)d_in[7];
    const float* b2 = (const float*)d_in[8];
    const float* W3 = (const float*)d_in[9];
    const float* b3 = (const float*)d_in[10];
    const float* Wih = (const float*)d_in[11];
    const float* Whh = (const float*)d_in[12];
    const float* bih = (const float*)d_in[13];
    const float* bhh = (const float*)d_in[14];

    void* tmp;
    cudaGetSymbolAddress(&tmp, g_nf);    float* p_nf = (float*)tmp;
    cudaGetSymbolAddress(&tmp, g_ef);    float* p_ef = (float*)tmp;
    cudaGetSymbolAddress(&tmp, g_rel);   float* p_rel = (float*)tmp;
    cudaGetSymbolAddress(&tmp, g_M);     float* p_M = (float*)tmp;
    cudaGetSymbolAddress(&tmp, g_Gs);    float* p_Gs = (float*)tmp;
    cudaGetSymbolAddress(&tmp, g_Gd);    float* p_Gd = (float*)tmp;
    cudaGetSymbolAddress(&tmp, g_Qs);    float* p_Qs = (float*)tmp;
    cudaGetSymbolAddress(&tmp, g_Grel);  float* p_Grel = (float*)tmp;
    cudaGetSymbolAddress(&tmp, g_Qrel);  float* p_Qrel = (float*)tmp;
    cudaGetSymbolAddress(&tmp, g_gh);    float* p_gh = (float*)tmp;
    cudaGetSymbolAddress(&tmp, g_emsg);  float* p_em = (float*)tmp;
    cudaGetSymbolAddress(&tmp, g_Wcomb); float* p_Wc = (float*)tmp;

    cudaFuncSetAttribute(tc_gemm_k, cudaFuncAttributeMaxDynamicSharedMemorySize, TC_SMEM);
    cudaFuncSetAttribute(tc_gru2_k, cudaFuncAttributeMaxDynamicSharedMemorySize, GRU_TC_SMEM);

    float* out_nf = (float*)d_out;
    const size_t NH = (size_t)Nn * Hd;
    const size_t EH = (size_t)Ee * Hd;
    float* out_ef = ((size_t)out_size >= NH + EH) ? out_nf + NH : p_ef;

    const int NB = (Nn + 63) / 64;     // node_update tiles
    const int EG = (Ee + 127) / 128;   // tc_gemm row tiles (2344)
    const int NG = (Nn + 127) / 128;   // 235
    const int RG = (Rr + 127) / 128;   // 2
    const int E64 = (Ee + 63) / 64;    // tc_gru2 tiles (4688)
    const int EWB = (Ee * 32 + 255) / 256;

    // layer-invariant graph structure
    zero_mask_deg_k<<<1024, 256>>>();
    build_mask_k<<<(Ee + 255) / 256, 256>>>(src, dst, ety);
    rel_count_k<<<Rr, 256>>>();
    rel_scan_k<<<1, 32>>>();
    rel_fill_k<<<Rr, 256>>>();

    for (int l = 0; l < 2; l++) {
        const float* nf_in = l ? p_nf : nf0;
        const float* ef_in = l ? p_ef : ef0;
        float* nf_out = l ? out_nf : p_nf;
        float* ef_out = l ? out_ef : p_ef;

        const float* W1l = W1 + (size_t)l * Hd * H3;
        const float* b1l = b1 + (size_t)l * Hd;
        const float* W2l = W2 + (size_t)l * Hd * H3;
        const float* b2l = b2 + (size_t)l * Hd;
        const float* W3l = W3 + (size_t)l * Hd * Hd;
        const float* b3l = b3 + (size_t)l * Hd;
        const float* Wihl = Wih + (size_t)l * H3 * Hd;
        const float* Whhl = Whh + (size_t)l * H3 * Hd;
        const float* bihl = bih + (size_t)l * H3;
        const float* bhhl = bhh + (size_t)l * H3;

        zero_agg_rel_k<<<1024, 256>>>();
        rel_sum_k<<<dim3(Rr, 8), Hd>>>(nf_in);
        rel_fin_k<<<Rr, Hd>>>();

        comp_M_k<<<H3, H3>>>(Wihl, W2l);
        comp_bc_k<<<3, 128>>>(Wihl, b2l, bihl);
        comb_W_k<<<(512 * Hd + 255) / 256, 256>>>(Whhl, W1l);

        // per-node precomputes (N-tiles fastest -> L2 reuse of A rows)
        tc_gemm_k<<<dim3(3, NG), 256, TC_SMEM>>>(nf_in, Nn, p_M + 128, H3, p_Gs, H3);
        tc_gemm_k<<<dim3(3, NG), 256, TC_SMEM>>>(nf_in, Nn, p_M + 256, H3, p_Gd, H3);
        tc_gemm_k<<<dim3(1, NG), 256, TC_SMEM>>>(nf_in, Nn, W1l + 128, H3, p_Qs, Hd);
        // per-relation precomputes
        tc_gemm_k<<<dim3(3, RG), 256, TC_SMEM>>>(p_rel, Rr, p_M, H3, p_Grel, H3);
        tc_gemm_k<<<dim3(1, RG), 256, TC_SMEM>>>(p_rel, Rr, W1l, H3, p_Qrel, Hd);
        // per-edge combined: gh (0:384) + msg_ef (384:512) in ONE launch
        tc_gemm_k<<<dim3(4, EG), 256, TC_SMEM>>>(ef_in, Ee, p_Wc, Hd, p_gh, 512);

        // GRU#1 elementwise + msg atomics -> g_emsg
        edge_phaseA_k<<<EWB, 256>>>(ef_in, src, dst, ety, bhhl, b1l);
        // fused gi2 GEMM + GRU#2 -> new ef (no g_gi2 intermediate)
        tc_gru2_k<<<E64, 256, GRU_TC_SMEM>>>(ef_in, Wihl, bihl, bhhl, ef_out);

        // node update
        node_update_k<<<NB, 256>>>(nf_in, W3l, b3l, nf_out);
    }
}

// round 16
// speedup vs baseline: 1.3886x; 1.3886x over previous
#include <cuda_runtime.h>
#include <math.h>
#include <stdint.h>

#define Nn 30000
#define Ee 300000
#define Hd 128
#define H3 384
#define Rr 200
#define SLOPE 0.22916666666666666f

// ---------------- scratch (__device__ globals; allocation-free) ----------------
__device__ __align__(16) unsigned char g_mask[(size_t)Rr * Nn];   // 6 MB
__device__ float g_deg[Nn];
__device__ float g_relsum[Rr * Hd];
__device__ int   g_relcnt[Rr];
__device__ int   g_roff[Rr + 1];
__device__ int   g_rfill[Rr];
__device__ int   g_rlist[2 * Ee];
__device__ __align__(16) float g_rel[Rr * Hd];
__device__ __align__(16) float g_agg[(size_t)Nn * Hd];
__device__ __align__(16) float g_nf[(size_t)Nn * Hd];
__device__ __align__(16) float g_ef[(size_t)Ee * Hd];
// factorization tables
__device__ __align__(16) float g_M[H3 * H3];          // Wih @ W2  [384,384]
__device__ __align__(16) float g_bc[H3];              // Wih @ b2 + bih
__device__ __align__(16) float g_Gs[(size_t)Nn * H3];
__device__ __align__(16) float g_Gd[(size_t)Nn * H3];
__device__ __align__(16) float g_Qs[(size_t)Nn * Hd];
__device__ __align__(16) float g_Grel[Rr * H3];
__device__ __align__(16) float g_Qrel[Rr * Hd];
__device__ __align__(16) float g_gh[(size_t)Ee * 512]; // [0:384)=ef@Whh^T, [384:512)=ef@W1c^T
__device__ __align__(16) float g_emsg[(size_t)Ee * Hd];
__device__ __align__(16) float g_gi2[(size_t)Ee * H3];
__device__ __align__(16) float g_Wcomb[512 * Hd];      // rows 0:384 = Whh, 384:512 = W1c

// ---------------- zero kernels ----------------
__global__ void zero_mask_deg_k() {
    size_t tid = (size_t)blockIdx.x * blockDim.x + threadIdx.x;
    size_t st = (size_t)gridDim.x * blockDim.x;
    uint32_t* m = (uint32_t*)g_mask;
    size_t mw = (size_t)Rr * Nn / 4;
    for (size_t i = tid; i < mw; i += st) m[i] = 0u;
    for (size_t i = tid; i < Nn; i += st) g_deg[i] = 0.f;
}

__global__ void zero_agg_rel_k() {
    size_t tid = (size_t)blockIdx.x * blockDim.x + threadIdx.x;
    size_t st = (size_t)gridDim.x * blockDim.x;
    size_t na = (size_t)Nn * Hd;
    for (size_t i = tid; i < na; i += st) g_agg[i] = 0.f;
    for (size_t i = tid; i < (size_t)Rr * Hd; i += st) g_relsum[i] = 0.f;
}

// ---------------- graph structure (built once; layer-invariant) ----------------
__global__ void build_mask_k(const int* __restrict__ src, const int* __restrict__ dst,
                             const int* __restrict__ ety) {
    int e = blockIdx.x * blockDim.x + threadIdx.x;
    if (e < Ee) {
        int t = ety[e];
        g_mask[(size_t)t * Nn + src[e]] = 1;
        g_mask[(size_t)t * Nn + dst[e]] = 1;
        atomicAdd(&g_deg[dst[e]], 1.f);
    }
}

__global__ void rel_count_k() {
    int r = blockIdx.x;
    int tid = threadIdx.x;
    const unsigned char* mrow = g_mask + (size_t)r * Nn;
    int cnt = 0;
    for (int n = tid; n < Nn; n += 256) cnt += mrow[n] ? 1 : 0;
    __shared__ int sred[256];
    sred[tid] = cnt;
    __syncthreads();
    for (int s = 128; s > 0; s >>= 1) {
        if (tid < s) sred[tid] += sred[tid + s];
        __syncthreads();
    }
    if (tid == 0) g_relcnt[r] = sred[0];
}

__global__ void rel_scan_k() {
    if (threadIdx.x == 0) {
        int a = 0;
        for (int r = 0; r < Rr; r++) {
            g_roff[r] = a;
            a += g_relcnt[r];
            g_rfill[r] = 0;
        }
        g_roff[Rr] = a;
    }
}

__global__ void rel_fill_k() {
    int r = blockIdx.x;
    const unsigned char* mrow = g_mask + (size_t)r * Nn;
    int base = g_roff[r];
    for (int n = threadIdx.x; n < Nn; n += 256) {
        if (mrow[n]) {
            int p = atomicAdd(&g_rfill[r], 1);
            g_rlist[base + p] = n;
        }
    }
}

__global__ void rel_sum_k(const float* __restrict__ nf) {
    int r = blockIdx.x, part = blockIdx.y, c = threadIdx.x;  // 128 threads
    int beg = g_roff[r], end = g_roff[r + 1];
    int len = end - beg;
    int s0 = beg + (int)(((long long)len * part) >> 3);
    int s1 = beg + (int)(((long long)len * (part + 1)) >> 3);
    __shared__ int sidx[256];
    float acc = 0.f;
    for (int b = s0; b < s1; b += 256) {
        int nb = min(256, s1 - b);
        for (int i = c; i < nb; i += 128) sidx[i] = g_rlist[b + i];
        __syncthreads();
#pragma unroll 4
        for (int i = 0; i < nb; i++) acc += nf[(size_t)sidx[i] * Hd + c];
        __syncthreads();
    }
    if (acc != 0.f) atomicAdd(&g_relsum[r * Hd + c], acc);
}

__global__ void rel_fin_k() {
    int r = blockIdx.x, c = threadIdx.x;
    int cnt = g_roff[r + 1] - g_roff[r];
    g_rel[r * Hd + c] = (cnt > 0) ? g_relsum[r * Hd + c] / (float)cnt : 0.f;
}

// ---------------- weight composition ----------------
__global__ void comp_M_k(const float* __restrict__ Wih, const float* __restrict__ W2) {
    int i = blockIdx.x;
    int j = threadIdx.x;
    __shared__ float wr[Hd];
    if (j < Hd) wr[j] = Wih[(size_t)i * Hd + j];
    __syncthreads();
    float acc = 0.f;
#pragma unroll 8
    for (int h = 0; h < Hd; h++) acc += wr[h] * W2[(size_t)h * H3 + j];
    g_M[i * H3 + j] = acc;
}

__global__ void comp_bc_k(const float* __restrict__ Wih, const float* __restrict__ b2,
                          const float* __restrict__ bih) {
    int i = blockIdx.x * blockDim.x + threadIdx.x;
    if (i < H3) {
        float acc = bih[i];
#pragma unroll 8
        for (int h = 0; h < Hd; h++) acc += Wih[(size_t)i * Hd + h] * b2[h];
        g_bc[i] = acc;
    }
}

// combined weight table: rows 0:384 = Whh (ldw Hd), rows 384:512 = W1 cols 256:384
__global__ void comb_W_k(const float* __restrict__ Whh, const float* __restrict__ W1) {
    int idx = blockIdx.x * 256 + threadIdx.x;
    if (idx < 512 * Hd) {
        int j = idx >> 7, k = idx & 127;
        g_Wcomb[idx] = (j < H3) ? Whh[(size_t)j * Hd + k]
                                : W1[(size_t)(j - H3) * H3 + 256 + k];
    }
}

// ---------------- 3xTF32 tensor-core GEMM ----------------
// grid: (n_tiles, row_tiles) — N fastest for L2 reuse of A row tiles.
#define TCPAD 36
#define TC_SMEM (4 * 128 * TCPAD * 4)   // 73728 bytes

__device__ __forceinline__ uint32_t f2tf32(float x) {
    uint32_t r;
    asm("cvt.rna.tf32.f32 %0, %1;" : "=r"(r) : "f"(x));
    return r;
}

#define MMA_TF32(C, A0, A1, A2, A3, B0, B1)                                        \
    asm volatile(                                                                  \
        "mma.sync.aligned.m16n8k8.row.col.f32.tf32.tf32.f32 "                      \
        "{%0,%1,%2,%3}, {%4,%5,%6,%7}, {%8,%9}, {%0,%1,%2,%3};"                    \
        : "+f"(C[0]), "+f"(C[1]), "+f"(C[2]), "+f"(C[3])                           \
        : "r"(A0), "r"(A1), "r"(A2), "r"(A3), "r"(B0), "r"(B1))

__global__ __launch_bounds__(256, 2) void tc_gemm_k(
    const float* __restrict__ A, int nrows,
    const float* __restrict__ W, int ldw,
    float* __restrict__ out, int ldo) {
    extern __shared__ __align__(16) float ts[];
    float* Ah = ts;                    // [128][TCPAD]
    float* Al = Ah + 128 * TCPAD;
    float* Bh = Al + 128 * TCPAD;
    float* Bl = Bh + 128 * TCPAD;

    int jb = blockIdx.x * 128;
    int r0 = blockIdx.y * 128;
    int tid = threadIdx.x;
    int lane = tid & 31;
    int wid = tid >> 5;
    int wm = (wid & 1) * 64;
    int wn = (wid >> 1) * 32;
    int gg = lane >> 2, qq = lane & 3;

    float c[4][4][4];
#pragma unroll
    for (int mf = 0; mf < 4; mf++)
#pragma unroll
        for (int nf = 0; nf < 4; nf++)
#pragma unroll
            for (int u = 0; u < 4; u++) c[mf][nf][u] = 0.f;

    int lr = tid >> 3;            // 0..31
    int lc = (tid & 7) * 4;       // 0..28

#pragma unroll 1
    for (int s = 0; s < 4; s++) {
        int ks = s * 32;
        __syncthreads();
#pragma unroll
        for (int p = 0; p < 4; p++) {
            int row = p * 32 + lr;
            const float* ap = A + (size_t)min(r0 + row, nrows - 1) * Hd + ks + lc;
            float4 v = *reinterpret_cast<const float4*>(ap);
            const float* wp = W + (size_t)(jb + row) * ldw + ks + lc;
            float4 u = *reinterpret_cast<const float4*>(wp);
            float* ah = &Ah[row * TCPAD + lc];
            float* al = &Al[row * TCPAD + lc];
            float* bh = &Bh[row * TCPAD + lc];
            float* bl = &Bl[row * TCPAD + lc];
            float hx;
            hx = __uint_as_float(f2tf32(v.x)); ah[0] = hx; al[0] = __uint_as_float(f2tf32(v.x - hx));
            hx = __uint_as_float(f2tf32(v.y)); ah[1] = hx; al[1] = __uint_as_float(f2tf32(v.y - hx));
            hx = __uint_as_float(f2tf32(v.z)); ah[2] = hx; al[2] = __uint_as_float(f2tf32(v.z - hx));
            hx = __uint_as_float(f2tf32(v.w)); ah[3] = hx; al[3] = __uint_as_float(f2tf32(v.w - hx));
            hx = __uint_as_float(f2tf32(u.x)); bh[0] = hx; bl[0] = __uint_as_float(f2tf32(u.x - hx));
            hx = __uint_as_float(f2tf32(u.y)); bh[1] = hx; bl[1] = __uint_as_float(f2tf32(u.y - hx));
            hx = __uint_as_float(f2tf32(u.z)); bh[2] = hx; bl[2] = __uint_as_float(f2tf32(u.z - hx));
            hx = __uint_as_float(f2tf32(u.w)); bh[3] = hx; bl[3] = __uint_as_float(f2tf32(u.w - hx));
        }
        __syncthreads();
#pragma unroll
        for (int k8 = 0; k8 < 32; k8 += 8) {
            uint32_t ahf[4][4], alf[4][4];
#pragma unroll
            for (int mf = 0; mf < 4; mf++) {
                int rr = wm + mf * 16 + gg;
                ahf[mf][0] = __float_as_uint(Ah[rr * TCPAD + k8 + qq]);
                ahf[mf][1] = __float_as_uint(Ah[(rr + 8) * TCPAD + k8 + qq]);
                ahf[mf][2] = __float_as_uint(Ah[rr * TCPAD + k8 + qq + 4]);
                ahf[mf][3] = __float_as_uint(Ah[(rr + 8) * TCPAD + k8 + qq + 4]);
                alf[mf][0] = __float_as_uint(Al[rr * TCPAD + k8 + qq]);
                alf[mf][1] = __float_as_uint(Al[(rr + 8) * TCPAD + k8 + qq]);
                alf[mf][2] = __float_as_uint(Al[rr * TCPAD + k8 + qq + 4]);
                alf[mf][3] = __float_as_uint(Al[(rr + 8) * TCPAD + k8 + qq + 4]);
            }
#pragma unroll
            for (int nf = 0; nf < 4; nf++) {
                int nn = wn + nf * 8 + gg;
                uint32_t bh0 = __float_as_uint(Bh[nn * TCPAD + k8 + qq]);
                uint32_t bh1 = __float_as_uint(Bh[nn * TCPAD + k8 + qq + 4]);
                uint32_t bl0 = __float_as_uint(Bl[nn * TCPAD + k8 + qq]);
                uint32_t bl1 = __float_as_uint(Bl[nn * TCPAD + k8 + qq + 4]);
#pragma unroll
                for (int mf = 0; mf < 4; mf++) {
                    MMA_TF32(c[mf][nf], ahf[mf][0], ahf[mf][1], ahf[mf][2], ahf[mf][3], bh0, bh1);
                    MMA_TF32(c[mf][nf], ahf[mf][0], ahf[mf][1], ahf[mf][2], ahf[mf][3], bl0, bl1);
                    MMA_TF32(c[mf][nf], alf[mf][0], alf[mf][1], alf[mf][2], alf[mf][3], bh0, bh1);
                }
            }
        }
    }

#pragma unroll
    for (int mf = 0; mf < 4; mf++) {
        int r = r0 + wm + mf * 16 + gg;
#pragma unroll
        for (int nf = 0; nf < 4; nf++) {
            int cc = jb + wn + nf * 8 + 2 * qq;
            if (r < nrows)
                *reinterpret_cast<float2*>(&out[(size_t)r * ldo + cc]) =
                    make_float2(c[mf][nf][0], c[mf][nf][1]);
            if (r + 8 < nrows)
                *reinterpret_cast<float2*>(&out[(size_t)(r + 8) * ldo + cc]) =
                    make_float2(c[mf][nf][2], c[mf][nf][3]);
        }
    }
}

// ---------------- node update: rrelu(agg/deg + nf@W3^T + b3) ----------------
__global__ __launch_bounds__(256) void node_update_k(
    const float* __restrict__ nf, const float* __restrict__ W3, const float* __restrict__ b3,
    float* __restrict__ out) {
    __shared__ __align__(16) float As[64][33];
    __shared__ __align__(16) float Bs[32][132];
    int n0 = blockIdx.x * 64;
    int tid = threadIdx.x;
    int tx = tid & 15, ty = tid >> 4;

    float c[4][8];
#pragma unroll
    for (int i = 0; i < 4; i++)
#pragma unroll
        for (int u = 0; u < 8; u++) c[i][u] = 0.f;

    int lcol = tid & 31;
    int lrow = tid >> 5;
    int bj = tid >> 1;
    int bhalf = (tid & 1) * 16;

    for (int k0 = 0; k0 < Hd; k0 += 32) {
#pragma unroll
        for (int i = 0; i < 8; i++) {
            int rr = lrow + i * 8;
            As[rr][lcol] = nf[(size_t)min(n0 + rr, Nn - 1) * Hd + k0 + lcol];
        }
#pragma unroll
        for (int i = 0; i < 4; i++) {
            float4 w = *reinterpret_cast<const float4*>(&W3[(size_t)bj * Hd + k0 + bhalf + i * 4]);
            Bs[bhalf + i * 4 + 0][bj] = w.x;
            Bs[bhalf + i * 4 + 1][bj] = w.y;
            Bs[bhalf + i * 4 + 2][bj] = w.z;
            Bs[bhalf + i * 4 + 3][bj] = w.w;
        }
        __syncthreads();
#pragma unroll
        for (int kk = 0; kk < 32; kk++) {
            float a[4];
#pragma unroll
            for (int i = 0; i < 4; i++) a[i] = As[ty * 4 + i][kk];
            const float4* bp = reinterpret_cast<const float4*>(&Bs[kk][0]);
            float4 b0 = bp[tx], b1 = bp[16 + tx];
#pragma unroll
            for (int i = 0; i < 4; i++) {
                c[i][0] += a[i] * b0.x; c[i][1] += a[i] * b0.y;
                c[i][2] += a[i] * b0.z; c[i][3] += a[i] * b0.w;
                c[i][4] += a[i] * b1.x; c[i][5] += a[i] * b1.y;
                c[i][6] += a[i] * b1.z; c[i][7] += a[i] * b1.w;
            }
        }
        __syncthreads();
    }

#pragma unroll
    for (int i = 0; i < 4; i++) {
        int n = n0 + ty * 4 + i;
        if (n < Nn) {
            float dg = g_deg[n];
            if (dg < 1.f) dg = 1.f;
            float inv = 1.f / dg;
#pragma unroll
            for (int u = 0; u < 8; u++) {
                int j = (u < 4) ? tx * 4 + u : 64 + tx * 4 + (u - 4);
                float v = c[i][u] + __ldg(&b3[j]) + g_agg[(size_t)n * Hd + j] * inv;
                out[(size_t)n * Hd + j] = (v >= 0.f) ? v : SLOPE * v;
            }
        }
    }
}

// ---------------- edge phase A: elementwise GRU#1 + msg atomics -> g_emsg ----------------
__device__ __forceinline__ float sigmoidf_(float x) { return 1.f / (1.f + expf(-x)); }

__global__ __launch_bounds__(256) void edge_phaseA_k(
    const float* __restrict__ ef,
    const int* __restrict__ src, const int* __restrict__ dst, const int* __restrict__ ety,
    const float* __restrict__ bhh, const float* __restrict__ b1) {
    int gidx = blockIdx.x * 256 + threadIdx.x;
    int e = gidx >> 5, q = gidx & 31;
    if (e >= Ee) return;
    int t = ety[e], s = src[e], d = dst[e];
    size_t ec = (size_t)e;

    const float4* gr = (const float4*)(g_Grel + (size_t)t * H3);
    const float4* gs = (const float4*)(g_Gs + (size_t)s * H3);
    const float4* gd = (const float4*)(g_Gd + (size_t)d * H3);
    const float4* gh = (const float4*)(g_gh + ec * 512);
    const float4* bc4 = (const float4*)g_bc;
    const float4* bh4 = (const float4*)bhh;
    float4 hv = ((const float4*)(ef + ec * Hd))[q];

    float o[4];
    {
        float4 gi0, gi1, gi2v, gh0, gh1, gh2;
        float4 a0 = gr[q],      b0 = gs[q],       c0 = gd[q];
        float4 a1 = gr[32 + q], b1v = gs[32 + q], c1 = gd[32 + q];
        float4 a2 = gr[64 + q], b2v = gs[64 + q], c2 = gd[64 + q];
        float4 e0v = bc4[q], e1v = bc4[32 + q], e2v = bc4[64 + q];
        gi0.x = a0.x + b0.x + c0.x + e0v.x; gi0.y = a0.y + b0.y + c0.y + e0v.y;
        gi0.z = a0.z + b0.z + c0.z + e0v.z; gi0.w = a0.w + b0.w + c0.w + e0v.w;
        gi1.x = a1.x + b1v.x + c1.x + e1v.x; gi1.y = a1.y + b1v.y + c1.y + e1v.y;
        gi1.z = a1.z + b1v.z + c1.z + e1v.z; gi1.w = a1.w + b1v.w + c1.w + e1v.w;
        gi2v.x = a2.x + b2v.x + c2.x + e2v.x; gi2v.y = a2.y + b2v.y + c2.y + e2v.y;
        gi2v.z = a2.z + b2v.z + c2.z + e2v.z; gi2v.w = a2.w + b2v.w + c2.w + e2v.w;
        float4 h0 = gh[q], h1 = gh[32 + q], h2 = gh[64 + q];
        float4 p0 = bh4[q], p1 = bh4[32 + q], p2 = bh4[64 + q];
        gh0.x = h0.x + p0.x; gh0.y = h0.y + p0.y; gh0.z = h0.z + p0.z; gh0.w = h0.w + p0.w;
        gh1.x = h1.x + p1.x; gh1.y = h1.y + p1.y; gh1.z = h1.z + p1.z; gh1.w = h1.w + p1.w;
        gh2.x = h2.x + p2.x; gh2.y = h2.y + p2.y; gh2.z = h2.z + p2.z; gh2.w = h2.w + p2.w;

        float rg, zg, ng;
        rg = sigmoidf_(gi0.x + gh0.x); zg = sigmoidf_(gi1.x + gh1.x);
        ng = tanhf(gi2v.x + rg * gh2.x); o[0] = (1.f - zg) * ng + zg * hv.x;
        rg = sigmoidf_(gi0.y + gh0.y); zg = sigmoidf_(gi1.y + gh1.y);
        ng = tanhf(gi2v.y + rg * gh2.y); o[1] = (1.f - zg) * ng + zg * hv.y;
        rg = sigmoidf_(gi0.z + gh0.z); zg = sigmoidf_(gi1.z + gh1.z);
        ng = tanhf(gi2v.z + rg * gh2.z); o[2] = (1.f - zg) * ng + zg * hv.z;
        rg = sigmoidf_(gi0.w + gh0.w); zg = sigmoidf_(gi1.w + gh1.w);
        ng = tanhf(gi2v.w + rg * gh2.w); o[3] = (1.f - zg) * ng + zg * hv.w;
    }
    *reinterpret_cast<float4*>(g_emsg + ec * Hd + q * 4) = make_float4(o[0], o[1], o[2], o[3]);

    // msg + atomic aggregation (mean divide happens in node_update)
    {
        const float4* qr = (const float4*)(g_Qrel + (size_t)t * Hd);
        const float4* qs = (const float4*)(g_Qs + (size_t)s * Hd);
        float4 me = ((const float4*)(g_gh + ec * 512 + 384))[q];
        float4 bb = ((const float4*)b1)[q];
        float4 qa = qr[q], qb = qs[q];
        float* ap = &g_agg[(size_t)d * Hd + q * 4];
        atomicAdd(ap + 0, qa.x + qb.x + me.x + bb.x);
        atomicAdd(ap + 1, qa.y + qb.y + me.y + bb.y);
        atomicAdd(ap + 2, qa.z + qb.z + me.z + bb.z);
        atomicAdd(ap + 3, qa.w + qb.w + me.w + bb.w);
    }
}

// ---------------- edge phase B: gi2 + gh -> GRU#2 -> new ef ----------------
__global__ __launch_bounds__(256) void edge_phaseB_k(
    const float* __restrict__ ef,
    const float* __restrict__ bih, const float* __restrict__ bhh,
    float* __restrict__ out) {
    int gidx = blockIdx.x * 256 + threadIdx.x;
    int e = gidx >> 5;
    int q = gidx & 31;
    if (e >= Ee) return;
    size_t ec = (size_t)e;

    const float4* gi = (const float4*)(g_gi2 + ec * H3);
    const float4* gh = (const float4*)(g_gh + ec * 512);
    const float4* bi4 = (const float4*)bih;
    const float4* bh4 = (const float4*)bhh;
    float4 hv = ((const float4*)(ef + ec * Hd))[q];

    float4 i0 = gi[q], i1 = gi[32 + q], i2 = gi[64 + q];
    float4 h0 = gh[q], h1 = gh[32 + q], h2 = gh[64 + q];
    float4 bi0 = bi4[q], bi1 = bi4[32 + q], bi2 = bi4[64 + q];
    float4 p0 = bh4[q], p1 = bh4[32 + q], p2 = bh4[64 + q];

    float4 o;
    float rg, zg, ng;
    rg = sigmoidf_((i0.x + bi0.x) + (h0.x + p0.x));
    zg = sigmoidf_((i1.x + bi1.x) + (h1.x + p1.x));
    ng = tanhf((i2.x + bi2.x) + rg * (h2.x + p2.x));
    o.x = (1.f - zg) * ng + zg * hv.x;
    rg = sigmoidf_((i0.y + bi0.y) + (h0.y + p0.y));
    zg = sigmoidf_((i1.y + bi1.y) + (h1.y + p1.y));
    ng = tanhf((i2.y + bi2.y) + rg * (h2.y + p2.y));
    o.y = (1.f - zg) * ng + zg * hv.y;
    rg = sigmoidf_((i0.z + bi0.z) + (h0.z + p0.z));
    zg = sigmoidf_((i1.z + bi1.z) + (h1.z + p1.z));
    ng = tanhf((i2.z + bi2.z) + rg * (h2.z + p2.z));
    o.z = (1.f - zg) * ng + zg * hv.z;
    rg = sigmoidf_((i0.w + bi0.w) + (h0.w + p0.w));
    zg = sigmoidf_((i1.w + bi1.w) + (h1.w + p1.w));
    ng = tanhf((i2.w + bi2.w) + rg * (h2.w + p2.w));
    o.w = (1.f - zg) * ng + zg * hv.w;

    *reinterpret_cast<float4*>(out + ec * Hd + q * 4) = o;
}

// ---------------- host orchestration ----------------
extern "C" void kernel_launch(void* const* d_in, const int* in_sizes, int n_in,
                              void* d_out, int out_size) {
    const float* nf0 = (const float*)d_in[0];
    const float* ef0 = (const float*)d_in[1];
    const int* src = (const int*)d_in[2];
    const int* dst = (const int*)d_in[3];
    const int* ety = (const int*)d_in[4];
    const float* W1 = (const float*)d_in[5];
    const float* b1 = (const float*)d_in[6];
    const float* W2 = (const float*)d_in[7];
    const float* b2 = (const float*)d_in[8];
    const float* W3 = (const float*)d_in[9];
    const float* b3 = (const float*)d_in[10];
    const float* Wih = (const float*)d_in[11];
    const float* Whh = (const float*)d_in[12];
    const float* bih = (const float*)d_in[13];
    const float* bhh = (const float*)d_in[14];

    void* tmp;
    cudaGetSymbolAddress(&tmp, g_nf);    float* p_nf = (float*)tmp;
    cudaGetSymbolAddress(&tmp, g_ef);    float* p_ef = (float*)tmp;
    cudaGetSymbolAddress(&tmp, g_rel);   float* p_rel = (float*)tmp;
    cudaGetSymbolAddress(&tmp, g_M);     float* p_M = (float*)tmp;
    cudaGetSymbolAddress(&tmp, g_Gs);    float* p_Gs = (float*)tmp;
    cudaGetSymbolAddress(&tmp, g_Gd);    float* p_Gd = (float*)tmp;
    cudaGetSymbolAddress(&tmp, g_Qs);    float* p_Qs = (float*)tmp;
    cudaGetSymbolAddress(&tmp, g_Grel);  float* p_Grel = (float*)tmp;
    cudaGetSymbolAddress(&tmp, g_Qrel);  float* p_Qrel = (float*)tmp;
    cudaGetSymbolAddress(&tmp, g_gh);    float* p_gh = (float*)tmp;
    cudaGetSymbolAddress(&tmp, g_emsg);  float* p_em = (float*)tmp;
    cudaGetSymbolAddress(&tmp, g_gi2);   float* p_gi2 = (float*)tmp;
    cudaGetSymbolAddress(&tmp, g_Wcomb); float* p_Wc = (float*)tmp;

    cudaFuncSetAttribute(tc_gemm_k, cudaFuncAttributeMaxDynamicSharedMemorySize, TC_SMEM);

    float* out_nf = (float*)d_out;
    const size_t NH = (size_t)Nn * Hd;
    const size_t EH = (size_t)Ee * Hd;
    float* out_ef = ((size_t)out_size >= NH + EH) ? out_nf + NH : p_ef;

    const int NB = (Nn + 63) / 64;     // node_update tiles
    const int EG = (Ee + 127) / 128;   // tc_gemm row tiles (2344)
    const int NG = (Nn + 127) / 128;   // 235
    const int RG = (Rr + 127) / 128;   // 2
    const int EWB = (Ee * 32 + 255) / 256;

    // layer-invariant graph structure
    zero_mask_deg_k<<<1024, 256>>>();
    build_mask_k<<<(Ee + 255) / 256, 256>>>(src, dst, ety);
    rel_count_k<<<Rr, 256>>>();
    rel_scan_k<<<1, 32>>>();
    rel_fill_k<<<Rr, 256>>>();

    for (int l = 0; l < 2; l++) {
        const float* nf_in = l ? p_nf : nf0;
        const float* ef_in = l ? p_ef : ef0;
        float* nf_out = l ? out_nf : p_nf;
        float* ef_out = l ? out_ef : p_ef;

        const float* W1l = W1 + (size_t)l * Hd * H3;
        const float* b1l = b1 + (size_t)l * Hd;
        const float* W2l = W2 + (size_t)l * Hd * H3;
        const float* b2l = b2 + (size_t)l * Hd;
        const float* W3l = W3 + (size_t)l * Hd * Hd;
        const float* b3l = b3 + (size_t)l * Hd;
        const float* Wihl = Wih + (size_t)l * H3 * Hd;
        const float* Whhl = Whh + (size_t)l * H3 * Hd;
        const float* bihl = bih + (size_t)l * H3;
        const float* bhhl = bhh + (size_t)l * H3;

        zero_agg_rel_k<<<1024, 256>>>();
        rel_sum_k<<<dim3(Rr, 8), Hd>>>(nf_in);
        rel_fin_k<<<Rr, Hd>>>();

        comp_M_k<<<H3, H3>>>(Wihl, W2l);
        comp_bc_k<<<3, 128>>>(Wihl, b2l, bihl);
        comb_W_k<<<(512 * Hd + 255) / 256, 256>>>(Whhl, W1l);

        // per-node precomputes (N-tiles fastest -> L2 reuse of A rows)
        tc_gemm_k<<<dim3(3, NG), 256, TC_SMEM>>>(nf_in, Nn, p_M + 128, H3, p_Gs, H3);
        tc_gemm_k<<<dim3(3, NG), 256, TC_SMEM>>>(nf_in, Nn, p_M + 256, H3, p_Gd, H3);
        tc_gemm_k<<<dim3(1, NG), 256, TC_SMEM>>>(nf_in, Nn, W1l + 128, H3, p_Qs, Hd);
        // per-relation precomputes
        tc_gemm_k<<<dim3(3, RG), 256, TC_SMEM>>>(p_rel, Rr, p_M, H3, p_Grel, H3);
        tc_gemm_k<<<dim3(1, RG), 256, TC_SMEM>>>(p_rel, Rr, W1l, H3, p_Qrel, Hd);
        // per-edge combined: gh (0:384) + msg_ef (384:512) in ONE launch
        tc_gemm_k<<<dim3(4, EG), 256, TC_SMEM>>>(ef_in, Ee, p_Wc, Hd, p_gh, 512);

        // GRU#1 elementwise + msg atomics -> g_emsg
        edge_phaseA_k<<<EWB, 256>>>(ef_in, src, dst, ety, bhhl, b1l);
        // gi2 = e_msg @ Wih^T (full-efficiency 128x128 tensor-core GEMM)
        tc_gemm_k<<<dim3(3, EG), 256, TC_SMEM>>>(p_em, Ee, Wihl, Hd, p_gi2, H3);
        // GRU#2 elementwise -> new ef
        edge_phaseB_k<<<EWB, 256>>>(ef_in, bihl, bhhl, ef_out);

        // node update
        node_update_k<<<NB, 256>>>(nf_in, W3l, b3l, nf_out);
    }
}